// round 5
// baseline (speedup 1.0000x reference)
#include <cuda_runtime.h>

// Problem constants (fixed shapes from reference setup_inputs):
//   x, out_ae : (16, 3, 512, 512) fp32
//   out_seg   : (16, 1, 512, 512) fp32
//   out       : scalar fp32 loss
#define N_      16
#define C_      3
#define HW_     (512 * 512)          // 262144
#define NHW_    (N_ * HW_)           // 4194304  (pos+neg total over (n,1,h,w))
#define HW4_    (HW_ / 4)            // 65536    (float4 units per plane)
#define NHW4_   (NHW_ / 4)           // 1048576  (float4 work items)
#define BF_THRESH 0.5f

#define BLOCK_THREADS 256
#define GRID_BLOCKS   1184           // 148 SMs x 8 blocks -> exactly ONE wave

// Device-global accumulators. Zero-initialized at module load; the
// finalizing block resets them so every graph replay starts clean.
__device__ float        g_pos_sum = 0.0f;
__device__ float        g_tot_sum = 0.0f;
__device__ float        g_pos_cnt = 0.0f;
__device__ unsigned int g_done    = 0u;

__global__ __launch_bounds__(BLOCK_THREADS, 8)   // pin <=32 regs -> 8 blocks/SM
void wmse_kernel(const float4* __restrict__ x4,
                 const float4* __restrict__ ae4,
                 const float4* __restrict__ seg4,
                 float* __restrict__ out)
{
    float pos_s = 0.0f;   // sum of diff^2 where seg > 0.5 (over all c)
    float tot_s = 0.0f;   // sum of diff^2 over everything
    float cnt   = 0.0f;   // count of seg > 0.5 (over n,h,w only)

    const int stride = GRID_BLOCKS * BLOCK_THREADS;   // 303104
    for (int g = blockIdx.x * BLOCK_THREADS + threadIdx.x; g < NHW4_; g += stride) {
        // g indexes float4 groups over (n, h*w/4). HW4_ = 65536 = 2^16.
        const int n   = g >> 16;
        const int hwq = g & 0xFFFF;

        // Streaming loads (evict-first): zero reuse, keep L2 out of the way.
        const float4 s = __ldcs(&seg4[g]);
        const float4 p = make_float4(s.x > BF_THRESH ? 1.0f : 0.0f,
                                     s.y > BF_THRESH ? 1.0f : 0.0f,
                                     s.z > BF_THRESH ? 1.0f : 0.0f,
                                     s.w > BF_THRESH ? 1.0f : 0.0f);
        cnt += (p.x + p.y) + (p.z + p.w);

        const int base = n * (C_ * HW4_) + hwq;
        #pragma unroll
        for (int c = 0; c < C_; ++c) {
            const float4 xv = __ldcs(&x4 [base + c * HW4_]);
            const float4 av = __ldcs(&ae4[base + c * HW4_]);
            const float dx = av.x - xv.x;
            const float dy = av.y - xv.y;
            const float dz = av.z - xv.z;
            const float dw = av.w - xv.w;
            const float ex = dx * dx, ey = dy * dy, ez = dz * dz, ew = dw * dw;
            tot_s += (ex + ey) + (ez + ew);
            pos_s += (ex * p.x + ey * p.y) + (ez * p.z + ew * p.w);
        }
    }

    // ---- intra-warp reduction ----
    #pragma unroll
    for (int o = 16; o > 0; o >>= 1) {
        pos_s += __shfl_down_sync(0xFFFFFFFFu, pos_s, o);
        tot_s += __shfl_down_sync(0xFFFFFFFFu, tot_s, o);
        cnt   += __shfl_down_sync(0xFFFFFFFFu, cnt,   o);
    }

    // ---- intra-block reduction (8 warps) ----
    __shared__ float sp[8], st[8], sc[8];
    const int wid = threadIdx.x >> 5;
    const int lid = threadIdx.x & 31;
    if (lid == 0) { sp[wid] = pos_s; st[wid] = tot_s; sc[wid] = cnt; }
    __syncthreads();

    if (threadIdx.x == 0) {
        float bp = 0.0f, bt = 0.0f, bc = 0.0f;
        #pragma unroll
        for (int i = 0; i < BLOCK_THREADS / 32; ++i) {
            bp += sp[i]; bt += st[i]; bc += sc[i];
        }

        atomicAdd(&g_pos_sum, bp);
        atomicAdd(&g_tot_sum, bt);
        atomicAdd(&g_pos_cnt, bc);
        __threadfence();

        const unsigned int ticket = atomicAdd(&g_done, 1u);
        if (ticket == GRID_BLOCKS - 1u) {
            // Last block: all partials globally visible (threadfence + atomic order).
            const float ps = atomicAdd(&g_pos_sum, 0.0f);
            const float ts = atomicAdd(&g_tot_sum, 0.0f);
            const float pn = atomicAdd(&g_pos_cnt, 0.0f);

            const float total     = (float)NHW_;
            const float neg_num   = total - pn;
            const float pos_ratio = pn / total;
            const float neg_ratio = 1.0f - pos_ratio;
            const float cf        = (float)C_;
            const float mse_pos   = ps / (pn * cf);
            const float mse_neg   = (ts - ps) / (neg_num * cf);
            out[0] = pos_ratio * mse_neg + neg_ratio * mse_pos;

            // Reset accumulators so the next graph replay starts clean.
            g_pos_sum = 0.0f;
            g_tot_sum = 0.0f;
            g_pos_cnt = 0.0f;
            __threadfence();
            g_done = 0u;
        }
    }
}

extern "C" void kernel_launch(void* const* d_in, const int* in_sizes, int n_in,
                              void* d_out, int out_size)
{
    const float4* x4   = (const float4*)d_in[0];   // x        (16,3,512,512)
    const float4* ae4  = (const float4*)d_in[1];   // out_ae   (16,3,512,512)
    const float4* seg4 = (const float4*)d_in[2];   // out_seg  (16,1,512,512)
    float* out = (float*)d_out;

    wmse_kernel<<<GRID_BLOCKS, BLOCK_THREADS>>>(x4, ae4, seg4, out);
}

// round 6
// speedup vs baseline: 1.0890x; 1.0890x over previous
#include <cuda_runtime.h>

// Problem constants (fixed shapes from reference setup_inputs):
//   x, out_ae : (16, 3, 512, 512) fp32
//   out_seg   : (16, 1, 512, 512) fp32
//   out       : scalar fp32 loss
#define N_      16
#define C_      3
#define HW_     (512 * 512)          // 262144
#define NHW_    (N_ * HW_)           // 4194304  (pos+neg total over (n,1,h,w))
#define HW4_    (HW_ / 4)            // 65536    (float4 units per plane)
#define NHW4_   (NHW_ / 4)           // 1048576  (float4 work items)
#define BF_THRESH 0.5f

#define BLOCK_THREADS 256
#define GRID_BLOCKS   592            // 148 SMs x 4 blocks -> one resident wave

// Device-global accumulators. Zero-initialized at module load; the
// finalizing block resets them so every graph replay starts clean.
__device__ float        g_pos_sum = 0.0f;
__device__ float        g_tot_sum = 0.0f;
__device__ float        g_pos_cnt = 0.0f;
__device__ unsigned int g_done    = 0u;

// 64-reg budget (4 blocks/SM): enough to hold ALL 7 float4 loads of an
// iteration in registers simultaneously -> MLP_eff ~= 7 per warp.
__global__ __launch_bounds__(BLOCK_THREADS, 4)
void wmse_kernel(const float4* __restrict__ x4,
                 const float4* __restrict__ ae4,
                 const float4* __restrict__ seg4,
                 float* __restrict__ out)
{
    float pos_s = 0.0f;   // sum of diff^2 where seg > 0.5 (over all c)
    float tot_s = 0.0f;   // sum of diff^2 over everything
    float cnt   = 0.0f;   // count of seg > 0.5 (over n,h,w only)

    const int stride = GRID_BLOCKS * BLOCK_THREADS;   // 151552
    for (int g = blockIdx.x * BLOCK_THREADS + threadIdx.x; g < NHW4_; g += stride) {
        // g indexes float4 groups over (n, h*w/4). HW4_ = 65536 = 2^16.
        const int n    = g >> 16;
        const int hwq  = g & 0xFFFF;
        const int base = n * (C_ * HW4_) + hwq;

        // ---- issue ALL 7 independent loads first (front-batched MLP) ----
        const float4 s   = seg4[g];
        const float4 xv0 = x4 [base + 0 * HW4_];
        const float4 av0 = ae4[base + 0 * HW4_];
        const float4 xv1 = x4 [base + 1 * HW4_];
        const float4 av1 = ae4[base + 1 * HW4_];
        const float4 xv2 = x4 [base + 2 * HW4_];
        const float4 av2 = ae4[base + 2 * HW4_];

        // ---- then compute ----
        const float px = s.x > BF_THRESH ? 1.0f : 0.0f;
        const float py = s.y > BF_THRESH ? 1.0f : 0.0f;
        const float pz = s.z > BF_THRESH ? 1.0f : 0.0f;
        const float pw = s.w > BF_THRESH ? 1.0f : 0.0f;
        cnt += (px + py) + (pz + pw);

        {
            const float dx = av0.x - xv0.x, dy = av0.y - xv0.y;
            const float dz = av0.z - xv0.z, dw = av0.w - xv0.w;
            const float ex = dx * dx, ey = dy * dy, ez = dz * dz, ew = dw * dw;
            tot_s += (ex + ey) + (ez + ew);
            pos_s += (ex * px + ey * py) + (ez * pz + ew * pw);
        }
        {
            const float dx = av1.x - xv1.x, dy = av1.y - xv1.y;
            const float dz = av1.z - xv1.z, dw = av1.w - xv1.w;
            const float ex = dx * dx, ey = dy * dy, ez = dz * dz, ew = dw * dw;
            tot_s += (ex + ey) + (ez + ew);
            pos_s += (ex * px + ey * py) + (ez * pz + ew * pw);
        }
        {
            const float dx = av2.x - xv2.x, dy = av2.y - xv2.y;
            const float dz = av2.z - xv2.z, dw = av2.w - xv2.w;
            const float ex = dx * dx, ey = dy * dy, ez = dz * dz, ew = dw * dw;
            tot_s += (ex + ey) + (ez + ew);
            pos_s += (ex * px + ey * py) + (ez * pz + ew * pw);
        }
    }

    // ---- intra-warp reduction ----
    #pragma unroll
    for (int o = 16; o > 0; o >>= 1) {
        pos_s += __shfl_down_sync(0xFFFFFFFFu, pos_s, o);
        tot_s += __shfl_down_sync(0xFFFFFFFFu, tot_s, o);
        cnt   += __shfl_down_sync(0xFFFFFFFFu, cnt,   o);
    }

    // ---- intra-block reduction (8 warps) ----
    __shared__ float sp[8], st[8], sc[8];
    const int wid = threadIdx.x >> 5;
    const int lid = threadIdx.x & 31;
    if (lid == 0) { sp[wid] = pos_s; st[wid] = tot_s; sc[wid] = cnt; }
    __syncthreads();

    if (threadIdx.x == 0) {
        float bp = 0.0f, bt = 0.0f, bc = 0.0f;
        #pragma unroll
        for (int i = 0; i < BLOCK_THREADS / 32; ++i) {
            bp += sp[i]; bt += st[i]; bc += sc[i];
        }

        atomicAdd(&g_pos_sum, bp);
        atomicAdd(&g_tot_sum, bt);
        atomicAdd(&g_pos_cnt, bc);
        __threadfence();

        const unsigned int ticket = atomicAdd(&g_done, 1u);
        if (ticket == GRID_BLOCKS - 1u) {
            // Last block: all partials globally visible (threadfence + atomic order).
            const float ps = atomicAdd(&g_pos_sum, 0.0f);
            const float ts = atomicAdd(&g_tot_sum, 0.0f);
            const float pn = atomicAdd(&g_pos_cnt, 0.0f);

            const float total     = (float)NHW_;
            const float neg_num   = total - pn;
            const float pos_ratio = pn / total;
            const float neg_ratio = 1.0f - pos_ratio;
            const float cf        = (float)C_;
            const float mse_pos   = ps / (pn * cf);
            const float mse_neg   = (ts - ps) / (neg_num * cf);
            out[0] = pos_ratio * mse_neg + neg_ratio * mse_pos;

            // Reset accumulators so the next graph replay starts clean.
            g_pos_sum = 0.0f;
            g_tot_sum = 0.0f;
            g_pos_cnt = 0.0f;
            __threadfence();
            g_done = 0u;
        }
    }
}

extern "C" void kernel_launch(void* const* d_in, const int* in_sizes, int n_in,
                              void* d_out, int out_size)
{
    const float4* x4   = (const float4*)d_in[0];   // x        (16,3,512,512)
    const float4* ae4  = (const float4*)d_in[1];   // out_ae   (16,3,512,512)
    const float4* seg4 = (const float4*)d_in[2];   // out_seg  (16,1,512,512)
    float* out = (float*)d_out;

    wmse_kernel<<<GRID_BLOCKS, BLOCK_THREADS>>>(x4, ae4, seg4, out);
}